// round 6
// baseline (speedup 1.0000x reference)
#include <cuda_runtime.h>
#include <cstddef>

#define BB   16
#define NPTS 10000
#define HID  128
#define OUTD 5
#define PTS  256
#define NT   40            // ceil(10000/256)
#define THR  512
#define ACTP 132           // plain-layout row stride (floats) for final stage

typedef unsigned long long u64;

__device__ float g_gate[BB * 4 * HID];
__device__ float g_bc[BB * OUTD * HID];

__device__ __forceinline__ float tanh_ap(float x) {
    float r; asm("tanh.approx.f32 %0, %1;" : "=f"(r) : "f"(x)); return r;
}
__device__ __forceinline__ float sin_ap(float x) {
    float r; asm("sin.approx.f32 %0, %1;" : "=f"(r) : "f"(x)); return r;
}
__device__ __forceinline__ u64 pk2(float x, float y) {
    u64 r; asm("mov.b64 %0, {%1, %2};" : "=l"(r) : "f"(x), "f"(y)); return r;
}
__device__ __forceinline__ float2 up2(u64 v) {
    float2 r; asm("mov.b64 {%0, %1}, %2;" : "=f"(r.x), "=f"(r.y) : "l"(v)); return r;
}
__device__ __forceinline__ void fma2(u64& d, u64 a, u64 b) {
    asm("fma.rn.f32x2 %0, %1, %2, %0;" : "+l"(d) : "l"(a), "l"(b));
}

// ---------------------------------------------------------------------------
// Branch MLP: 16 blocks x 256 threads. Unchanged.
// ---------------------------------------------------------------------------
__global__ void branch_kernel(const float* __restrict__ params,
                              const float* __restrict__ Wb0, const float* __restrict__ bb0,
                              const float* __restrict__ Wb,  const float* __restrict__ bbv,
                              const float* __restrict__ Wbf, const float* __restrict__ bbf,
                              const float* __restrict__ ab,  const float* __restrict__ wb)
{
    __shared__ float h_s[HID];
    __shared__ float part[HID];
    const int b = blockIdx.x, tid = threadIdx.x;
    const int j = tid & 127, hh = tid >> 7;

    float g = 0.f;
    if (hh == 0) {
        float z = bb0[j];
#pragma unroll
        for (int c = 0; c < 6; ++c) z = fmaf(params[b * 6 + c], Wb0[c * HID + j], z);
        float v = tanh_ap(z) + ab[j] * sin_ap(wb[j] * z);
        g = v; g_gate[(b * 4) * HID + j] = g; h_s[j] = v;
    }
    __syncthreads();

    for (int i = 0; i < 3; ++i) {
        const float* W = Wb + (size_t)i * HID * HID;
        float zz = (hh == 0) ? bbv[i * HID + j] : 0.f;
        const int k0 = hh * 64;
#pragma unroll 4
        for (int k = 0; k < 64; ++k) zz = fmaf(h_s[k0 + k], W[(size_t)(k0 + k) * HID + j], zz);
        if (hh) part[j] = zz;
        __syncthreads();
        float v = 0.f;
        if (hh == 0) {
            float z = zz + part[j];
            v = tanh_ap(z) + ab[(i + 1) * HID + j] * sin_ap(wb[(i + 1) * HID + j] * z);
            g += v; g_gate[(b * 4 + i + 1) * HID + j] = g;
        }
        __syncthreads();
        if (hh == 0) h_s[j] = v;
        __syncthreads();
    }

#pragma unroll
    for (int o = 0; o < OUTD; ++o) {
        float zz = (hh == 0) ? bbf[o * HID + j] : 0.f;
        const int k0 = hh * 64;
#pragma unroll 4
        for (int k = 0; k < 64; ++k)
            zz = fmaf(h_s[k0 + k], Wbf[(size_t)(k0 + k) * (HID * OUTD) + o * HID + j], zz);
        if (hh) part[j] = zz;
        __syncthreads();
        if (hh == 0) g_bc[(b * OUTD + o) * HID + j] = zz + part[j];
        __syncthreads();
    }
}

// ---------------------------------------------------------------------------
// Fused trunk, 512 threads, PTS=256. Warp w owns 16 points = 8 pairs
// [8w, 8w+8). Lane owns 4 features f0=4*lane. Acts pair-interleaved
// ([pair][k][2]); GEMM in packed fma.rn.f32x2. k-step 2: weights amortized
// over 16 points -> LDS wavefronts at 0.5x of FMA-pipe cycles.
// ---------------------------------------------------------------------------
__global__ void __launch_bounds__(THR, 1)
trunk_kernel(const float* __restrict__ coords, const float* __restrict__ sdf,
             const float* __restrict__ Wt0, const float* __restrict__ bt0,
             const float* __restrict__ Wt,  const float* __restrict__ btv,
             const float* __restrict__ Wtf, const float* __restrict__ btf,
             const float* __restrict__ at,  const float* __restrict__ wt,
             float* __restrict__ out)
{
    extern __shared__ float sm[];
    float* sW = sm;                   // 128*128 = 16384
    float* sA = sW + HID * HID;       // max(128*256 pair, 256*132 plain) = 33792
    float* sX = sA + 33792;           // 256*4 = 1024
    float* sG = sX + PTS * 4;         // 512
    float* sC = sG + 4 * HID;         // 640
    // total 52352 floats = 209408 bytes

    const int b    = blockIdx.y;
    const int p0   = blockIdx.x * PTS;
    const int tid  = threadIdx.x;
    const int w    = tid >> 5;        // warp 0..15
    const int lane = tid & 31;
    const int f0   = lane * 4;

    // stage inputs
    if (tid < PTS) {
        int p = p0 + tid;
        float4 v = make_float4(0.f, 0.f, 0.f, 0.f);
        if (p < NPTS) {
            const float* c = coords + ((size_t)b * NPTS + p) * 3;
            v.x = c[0]; v.y = c[1]; v.z = c[2];
            v.w = sdf[(size_t)b * NPTS + p];
        }
        ((float4*)sX)[tid] = v;
    }
    for (int i = tid; i < 4 * HID;    i += THR) sG[i] = g_gate[b * 4 * HID + i];
    for (int i = tid; i < OUTD * HID; i += THR) sC[i] = g_bc[b * OUTD * HID + i];

    float* base = sA + (w * 8) * 256;   // this warp's 8 pair rows

    // ---- layer 0: (coords,sdf) -> 128, rowdy * gate0 ----
    {
        float4 wd0 = *(const float4*)(Wt0 + 0 * HID + f0);
        float4 wd1 = *(const float4*)(Wt0 + 1 * HID + f0);
        float4 wd2 = *(const float4*)(Wt0 + 2 * HID + f0);
        float4 wd3 = *(const float4*)(Wt0 + 3 * HID + f0);
        float4 bias4 = *(const float4*)(bt0 + f0);
        float4 a4    = *(const float4*)(at + f0);
        float4 wq4   = *(const float4*)(wt + f0);
        __syncthreads();
        float4 g4 = *(const float4*)(sG + f0);
        const float* W0 = (const float*)&wd0; const float* W1 = (const float*)&wd1;
        const float* W2 = (const float*)&wd2; const float* W3 = (const float*)&wd3;
        const float* Bv = (const float*)&bias4; const float* Av = (const float*)&a4;
        const float* Qv = (const float*)&wq4;  const float* Gv = (const float*)&g4;
#pragma unroll
        for (int pq = 0; pq < 8; ++pq) {
            float4 x0 = ((float4*)sX)[w * 16 + pq * 2];
            float4 x1 = ((float4*)sX)[w * 16 + pq * 2 + 1];
            float r0[4], r1[4];
#pragma unroll
            for (int c = 0; c < 4; ++c) {
                float za = fmaf(x0.x, W0[c], fmaf(x0.y, W1[c], fmaf(x0.z, W2[c], fmaf(x0.w, W3[c], Bv[c]))));
                float zb = fmaf(x1.x, W0[c], fmaf(x1.y, W1[c], fmaf(x1.z, W2[c], fmaf(x1.w, W3[c], Bv[c]))));
                r0[c] = (tanh_ap(za) + Av[c] * sin_ap(Qv[c] * za)) * Gv[c];
                r1[c] = (tanh_ap(zb) + Av[c] * sin_ap(Qv[c] * zb)) * Gv[c];
            }
            float* rp = base + pq * 256 + 2 * f0;
            *(float4*)(rp)     = make_float4(r0[0], r1[0], r0[1], r1[1]);
            *(float4*)(rp + 4) = make_float4(r0[2], r1[2], r0[3], r1[3]);
        }
    }
    __syncwarp();

    // ---- layers 1..3 (rowdy*gate) and final linear (Wtf) ----
    for (int layer = 0; layer < 4; ++layer) {
        const float* Wsrc = (layer < 3) ? (Wt + (size_t)layer * HID * HID) : Wtf;
        const bool fin = (layer == 3);

        __syncthreads();                      // prior sW reads + (final) layout switch
        for (int i = tid; i < (HID * HID) / 4; i += THR)
            ((float4*)sW)[i] = ((const float4*)Wsrc)[i];
        __syncthreads();                      // sW ready

        u64 acc[8][4];
#pragma unroll
        for (int pq = 0; pq < 8; ++pq)
#pragma unroll
            for (int c = 0; c < 4; ++c) acc[pq][c] = 0ull;

#pragma unroll 1
        for (int k = 0; k < HID; k += 2) {
            const float* wp = sW + k * HID + f0;
            float4 wr0 = *(const float4*)(wp);
            float4 wr1 = *(const float4*)(wp + HID);
            u64 W0x = pk2(wr0.x, wr0.x), W0y = pk2(wr0.y, wr0.y);
            u64 W0z = pk2(wr0.z, wr0.z), W0w = pk2(wr0.w, wr0.w);
            u64 W1x = pk2(wr1.x, wr1.x), W1y = pk2(wr1.y, wr1.y);
            u64 W1z = pk2(wr1.z, wr1.z), W1w = pk2(wr1.w, wr1.w);
#pragma unroll
            for (int pq = 0; pq < 8; ++pq) {
                ulonglong2 a = *(const ulonglong2*)(base + pq * 256 + 2 * k);
                fma2(acc[pq][0], a.x, W0x); fma2(acc[pq][1], a.x, W0y);
                fma2(acc[pq][2], a.x, W0z); fma2(acc[pq][3], a.x, W0w);
                fma2(acc[pq][0], a.y, W1x); fma2(acc[pq][1], a.y, W1y);
                fma2(acc[pq][2], a.y, W1z); fma2(acc[pq][3], a.y, W1w);
            }
        }

        // scalars loaded AFTER the GEMM so they are not live across it
        float4 bias4, a4, wq4, g4;
        if (!fin) {
            bias4 = *(const float4*)(btv + layer * HID + f0);
            a4    = *(const float4*)(at + (layer + 1) * HID + f0);
            wq4   = *(const float4*)(wt + (layer + 1) * HID + f0);
            g4    = *(const float4*)(sG + (layer + 1) * HID + f0);
        } else {
            bias4 = *(const float4*)(btf + f0);
            a4 = wq4 = g4 = make_float4(0.f, 0.f, 0.f, 0.f);
        }
        const float* Bv = (const float*)&bias4; const float* Av = (const float*)&a4;
        const float* Qv = (const float*)&wq4;  const float* Gv = (const float*)&g4;

        if (!fin) {
            __syncwarp();                      // warp's reads of its rows done
#pragma unroll
            for (int pq = 0; pq < 8; ++pq) {
                float r0[4], r1[4];
#pragma unroll
                for (int c = 0; c < 4; ++c) {
                    float2 v = up2(acc[pq][c]);
                    float za = v.x + Bv[c], zb = v.y + Bv[c];
                    r0[c] = (tanh_ap(za) + Av[c] * sin_ap(Qv[c] * za)) * Gv[c];
                    r1[c] = (tanh_ap(zb) + Av[c] * sin_ap(Qv[c] * zb)) * Gv[c];
                }
                float* rp = base + pq * 256 + 2 * f0;
                *(float4*)(rp)     = make_float4(r0[0], r1[0], r0[1], r1[1]);
                *(float4*)(rp + 4) = make_float4(r0[2], r1[2], r0[3], r1[3]);
            }
            __syncwarp();
        } else {
            __syncthreads();                   // ALL pair-layout reads done before plain writes
#pragma unroll
            for (int pq = 0; pq < 8; ++pq) {
                const int p = w * 16 + pq * 2;
#pragma unroll
                for (int c = 0; c < 4; ++c) {
                    float2 v = up2(acc[pq][c]);
                    sA[p * ACTP + f0 + c]       = v.x + Bv[c];
                    sA[(p + 1) * ACTP + f0 + c] = v.y + Bv[c];
                }
            }
        }
    }
    __syncthreads();

    // ---- final contraction (f32x2): out[p][o] = sum_h trunk[p][h]*bc[o][h] ----
    if (tid < PTS) {
        const int p = tid;
        u64 q0 = 0ull, q1 = 0ull, q2 = 0ull, q3 = 0ull, q4 = 0ull;
#pragma unroll 4
        for (int h = 0; h < HID; h += 4) {
            ulonglong2 a  = *(const ulonglong2*)&sA[p * ACTP + h];
            ulonglong2 c0 = *(const ulonglong2*)&sC[0 * HID + h];
            ulonglong2 c1 = *(const ulonglong2*)&sC[1 * HID + h];
            ulonglong2 c2 = *(const ulonglong2*)&sC[2 * HID + h];
            ulonglong2 c3 = *(const ulonglong2*)&sC[3 * HID + h];
            ulonglong2 c4 = *(const ulonglong2*)&sC[4 * HID + h];
            fma2(q0, a.x, c0.x); fma2(q0, a.y, c0.y);
            fma2(q1, a.x, c1.x); fma2(q1, a.y, c1.y);
            fma2(q2, a.x, c2.x); fma2(q2, a.y, c2.y);
            fma2(q3, a.x, c3.x); fma2(q3, a.y, c3.y);
            fma2(q4, a.x, c4.x); fma2(q4, a.y, c4.y);
        }
        const int pglob = p0 + p;
        if (pglob < NPTS) {
            float2 v0 = up2(q0), v1 = up2(q1), v2 = up2(q2), v3 = up2(q3), v4 = up2(q4);
            float* dst = out + ((size_t)b * NPTS + pglob) * OUTD;
            dst[0] = v0.x + v0.y; dst[1] = v1.x + v1.y; dst[2] = v2.x + v2.y;
            dst[3] = v3.x + v3.y; dst[4] = v4.x + v4.y;
        }
    }
}

// ---------------------------------------------------------------------------
extern "C" void kernel_launch(void* const* d_in, const int* in_sizes, int n_in,
                              void* d_out, int out_size)
{
    const float* coords = (const float*)d_in[0];
    const float* sdf    = (const float*)d_in[1];
    const float* params = (const float*)d_in[2];
    const float* Wb0    = (const float*)d_in[3];
    const float* bb0    = (const float*)d_in[4];
    const float* Wb     = (const float*)d_in[5];
    const float* bbv    = (const float*)d_in[6];
    const float* Wbf    = (const float*)d_in[7];
    const float* bbf    = (const float*)d_in[8];
    const float* ab     = (const float*)d_in[9];
    const float* wb     = (const float*)d_in[10];
    const float* Wt0    = (const float*)d_in[11];
    const float* bt0    = (const float*)d_in[12];
    const float* Wt     = (const float*)d_in[13];
    const float* bt     = (const float*)d_in[14];
    const float* Wtf    = (const float*)d_in[15];
    const float* btf    = (const float*)d_in[16];
    const float* at     = (const float*)d_in[17];
    const float* wt     = (const float*)d_in[18];
    float* out = (float*)d_out;

    const size_t smem_bytes = (size_t)(HID * HID + 33792 + PTS * 4 + 4 * HID + OUTD * HID) * sizeof(float);
    cudaFuncSetAttribute(trunk_kernel, cudaFuncAttributeMaxDynamicSharedMemorySize, (int)smem_bytes);

    branch_kernel<<<BB, 256>>>(params, Wb0, bb0, Wb, bbv, Wbf, bbf, ab, wb);

    dim3 grid(NT, BB);
    trunk_kernel<<<grid, THR, smem_bytes>>>(coords, sdf, Wt0, bt0, Wt, bt,
                                            Wtf, btf, at, wt, out);
}

// round 7
// speedup vs baseline: 1.0930x; 1.0930x over previous
#include <cuda_runtime.h>
#include <cstddef>

#define BB   16
#define NPTS 10000
#define HID  128
#define OUTD 5
#define PTS  192
#define NT   53            // ceil(10000/192)
#define THR  512
#define ACTP 132           // plain-layout row stride (floats) for final stage
#define PAIRS 6            // pairs per warp (12 points)

typedef unsigned long long u64;

__device__ float g_gate[BB * 4 * HID];
__device__ float g_bc[BB * OUTD * HID];

__device__ __forceinline__ float tanh_ap(float x) {
    float r; asm("tanh.approx.f32 %0, %1;" : "=f"(r) : "f"(x)); return r;
}
__device__ __forceinline__ float sin_ap(float x) {
    float r; asm("sin.approx.f32 %0, %1;" : "=f"(r) : "f"(x)); return r;
}
__device__ __forceinline__ u64 pk2(float x, float y) {
    u64 r; asm("mov.b64 %0, {%1, %2};" : "=l"(r) : "f"(x), "f"(y)); return r;
}
__device__ __forceinline__ float2 up2(u64 v) {
    float2 r; asm("mov.b64 {%0, %1}, %2;" : "=f"(r.x), "=f"(r.y) : "l"(v)); return r;
}
__device__ __forceinline__ void fma2(u64& d, u64 a, u64 b) {
    asm("fma.rn.f32x2 %0, %1, %2, %0;" : "+l"(d) : "l"(a), "l"(b));
}

// ---------------------------------------------------------------------------
// Branch MLP: 16 blocks x 256 threads. Unchanged.
// ---------------------------------------------------------------------------
__global__ void branch_kernel(const float* __restrict__ params,
                              const float* __restrict__ Wb0, const float* __restrict__ bb0,
                              const float* __restrict__ Wb,  const float* __restrict__ bbv,
                              const float* __restrict__ Wbf, const float* __restrict__ bbf,
                              const float* __restrict__ ab,  const float* __restrict__ wb)
{
    __shared__ float h_s[HID];
    __shared__ float part[HID];
    const int b = blockIdx.x, tid = threadIdx.x;
    const int j = tid & 127, hh = tid >> 7;

    float g = 0.f;
    if (hh == 0) {
        float z = bb0[j];
#pragma unroll
        for (int c = 0; c < 6; ++c) z = fmaf(params[b * 6 + c], Wb0[c * HID + j], z);
        float v = tanh_ap(z) + ab[j] * sin_ap(wb[j] * z);
        g = v; g_gate[(b * 4) * HID + j] = g; h_s[j] = v;
    }
    __syncthreads();

    for (int i = 0; i < 3; ++i) {
        const float* W = Wb + (size_t)i * HID * HID;
        float zz = (hh == 0) ? bbv[i * HID + j] : 0.f;
        const int k0 = hh * 64;
#pragma unroll 4
        for (int k = 0; k < 64; ++k) zz = fmaf(h_s[k0 + k], W[(size_t)(k0 + k) * HID + j], zz);
        if (hh) part[j] = zz;
        __syncthreads();
        float v = 0.f;
        if (hh == 0) {
            float z = zz + part[j];
            v = tanh_ap(z) + ab[(i + 1) * HID + j] * sin_ap(wb[(i + 1) * HID + j] * z);
            g += v; g_gate[(b * 4 + i + 1) * HID + j] = g;
        }
        __syncthreads();
        if (hh == 0) h_s[j] = v;
        __syncthreads();
    }

#pragma unroll
    for (int o = 0; o < OUTD; ++o) {
        float zz = (hh == 0) ? bbf[o * HID + j] : 0.f;
        const int k0 = hh * 64;
#pragma unroll 4
        for (int k = 0; k < 64; ++k)
            zz = fmaf(h_s[k0 + k], Wbf[(size_t)(k0 + k) * (HID * OUTD) + o * HID + j], zz);
        if (hh) part[j] = zz;
        __syncthreads();
        if (hh == 0) g_bc[(b * OUTD + o) * HID + j] = zz + part[j];
        __syncthreads();
    }
}

// ---------------------------------------------------------------------------
// Fused trunk, 512 threads, PTS=192. Warp w owns 12 points = 6 pairs.
// Lane owns 4 features f0=4*lane. Acts pair-interleaved ([pair][h][2]);
// GEMM in packed fma.rn.f32x2 with acc[6][4] u64 (48 regs).
// ---------------------------------------------------------------------------
__global__ void __launch_bounds__(THR, 1)
trunk_kernel(const float* __restrict__ coords, const float* __restrict__ sdf,
             const float* __restrict__ Wt0, const float* __restrict__ bt0,
             const float* __restrict__ Wt,  const float* __restrict__ btv,
             const float* __restrict__ Wtf, const float* __restrict__ btf,
             const float* __restrict__ at,  const float* __restrict__ wt,
             float* __restrict__ out)
{
    extern __shared__ float sm[];
    float* sW = sm;                   // 128*128 = 16384
    float* sA = sW + HID * HID;       // max(96*256 pair, 192*132 plain) = 25344
    float* sX = sA + 25344;           // 192*4 = 768
    float* sG = sX + PTS * 4;         // 512
    float* sC = sG + 4 * HID;         // 640
    // total 43648 floats = 174592 bytes

    const int b    = blockIdx.y;
    const int p0   = blockIdx.x * PTS;
    const int tid  = threadIdx.x;
    const int w    = tid >> 5;        // warp 0..15
    const int lane = tid & 31;
    const int f0   = lane * 4;

    // stage inputs
    if (tid < PTS) {
        int p = p0 + tid;
        float4 v = make_float4(0.f, 0.f, 0.f, 0.f);
        if (p < NPTS) {
            const float* c = coords + ((size_t)b * NPTS + p) * 3;
            v.x = c[0]; v.y = c[1]; v.z = c[2];
            v.w = sdf[(size_t)b * NPTS + p];
        }
        ((float4*)sX)[tid] = v;
    }
    for (int i = tid; i < 4 * HID;    i += THR) sG[i] = g_gate[b * 4 * HID + i];
    for (int i = tid; i < OUTD * HID; i += THR) sC[i] = g_bc[b * OUTD * HID + i];

    float* base = sA + (w * PAIRS) * 256;   // this warp's 6 pair rows

    // ---- layer 0: (coords,sdf) -> 128, rowdy * gate0 ----
    {
        float4 wd0 = *(const float4*)(Wt0 + 0 * HID + f0);
        float4 wd1 = *(const float4*)(Wt0 + 1 * HID + f0);
        float4 wd2 = *(const float4*)(Wt0 + 2 * HID + f0);
        float4 wd3 = *(const float4*)(Wt0 + 3 * HID + f0);
        float4 bias4 = *(const float4*)(bt0 + f0);
        float4 a4    = *(const float4*)(at + f0);
        float4 wq4   = *(const float4*)(wt + f0);
        __syncthreads();
        float4 g4 = *(const float4*)(sG + f0);
        const float* W0 = (const float*)&wd0; const float* W1 = (const float*)&wd1;
        const float* W2 = (const float*)&wd2; const float* W3 = (const float*)&wd3;
        const float* Bv = (const float*)&bias4; const float* Av = (const float*)&a4;
        const float* Qv = (const float*)&wq4;  const float* Gv = (const float*)&g4;
#pragma unroll
        for (int pq = 0; pq < PAIRS; ++pq) {
            float4 x0 = ((float4*)sX)[w * (2 * PAIRS) + pq * 2];
            float4 x1 = ((float4*)sX)[w * (2 * PAIRS) + pq * 2 + 1];
            float r0[4], r1[4];
#pragma unroll
            for (int c = 0; c < 4; ++c) {
                float za = fmaf(x0.x, W0[c], fmaf(x0.y, W1[c], fmaf(x0.z, W2[c], fmaf(x0.w, W3[c], Bv[c]))));
                float zb = fmaf(x1.x, W0[c], fmaf(x1.y, W1[c], fmaf(x1.z, W2[c], fmaf(x1.w, W3[c], Bv[c]))));
                r0[c] = (tanh_ap(za) + Av[c] * sin_ap(Qv[c] * za)) * Gv[c];
                r1[c] = (tanh_ap(zb) + Av[c] * sin_ap(Qv[c] * zb)) * Gv[c];
            }
            float* rp = base + pq * 256 + 2 * f0;
            *(float4*)(rp)     = make_float4(r0[0], r1[0], r0[1], r1[1]);
            *(float4*)(rp + 4) = make_float4(r0[2], r1[2], r0[3], r1[3]);
        }
    }
    __syncwarp();

    // ---- layers 1..3 (rowdy*gate) and final linear (Wtf) ----
    for (int layer = 0; layer < 4; ++layer) {
        const float* Wsrc = (layer < 3) ? (Wt + (size_t)layer * HID * HID) : Wtf;
        const bool fin = (layer == 3);

        __syncthreads();                      // prior sW reads done everywhere
        for (int i = tid; i < (HID * HID) / 4; i += THR)
            ((float4*)sW)[i] = ((const float4*)Wsrc)[i];
        __syncthreads();                      // sW ready

        u64 acc[PAIRS][4];
#pragma unroll
        for (int pq = 0; pq < PAIRS; ++pq)
#pragma unroll
            for (int c = 0; c < 4; ++c) acc[pq][c] = 0ull;

#pragma unroll 1
        for (int k = 0; k < HID; k += 2) {
            const float* wp = sW + k * HID + f0;
            float4 wr0 = *(const float4*)(wp);
            float4 wr1 = *(const float4*)(wp + HID);
            u64 W0x = pk2(wr0.x, wr0.x), W0y = pk2(wr0.y, wr0.y);
            u64 W0z = pk2(wr0.z, wr0.z), W0w = pk2(wr0.w, wr0.w);
            u64 W1x = pk2(wr1.x, wr1.x), W1y = pk2(wr1.y, wr1.y);
            u64 W1z = pk2(wr1.z, wr1.z), W1w = pk2(wr1.w, wr1.w);
#pragma unroll
            for (int pq = 0; pq < PAIRS; ++pq) {
                ulonglong2 a = *(const ulonglong2*)(base + pq * 256 + 2 * k);
                fma2(acc[pq][0], a.x, W0x); fma2(acc[pq][1], a.x, W0y);
                fma2(acc[pq][2], a.x, W0z); fma2(acc[pq][3], a.x, W0w);
                fma2(acc[pq][0], a.y, W1x); fma2(acc[pq][1], a.y, W1y);
                fma2(acc[pq][2], a.y, W1z); fma2(acc[pq][3], a.y, W1w);
            }
        }

        // scalars loaded AFTER the GEMM so they are not live across it
        float4 bias4, a4, wq4, g4;
        if (!fin) {
            bias4 = *(const float4*)(btv + layer * HID + f0);
            a4    = *(const float4*)(at + (layer + 1) * HID + f0);
            wq4   = *(const float4*)(wt + (layer + 1) * HID + f0);
            g4    = *(const float4*)(sG + (layer + 1) * HID + f0);
        } else {
            bias4 = *(const float4*)(btf + f0);
            a4 = wq4 = g4 = make_float4(0.f, 0.f, 0.f, 0.f);
        }
        const float* Bv = (const float*)&bias4; const float* Av = (const float*)&a4;
        const float* Qv = (const float*)&wq4;  const float* Gv = (const float*)&g4;

        if (!fin) {
            __syncwarp();                      // warp's reads of its rows done
#pragma unroll
            for (int pq = 0; pq < PAIRS; ++pq) {
                float r0[4], r1[4];
#pragma unroll
                for (int c = 0; c < 4; ++c) {
                    float2 v = up2(acc[pq][c]);
                    float za = v.x + Bv[c], zb = v.y + Bv[c];
                    r0[c] = (tanh_ap(za) + Av[c] * sin_ap(Qv[c] * za)) * Gv[c];
                    r1[c] = (tanh_ap(zb) + Av[c] * sin_ap(Qv[c] * zb)) * Gv[c];
                }
                float* rp = base + pq * 256 + 2 * f0;
                *(float4*)(rp)     = make_float4(r0[0], r1[0], r0[1], r1[1]);
                *(float4*)(rp + 4) = make_float4(r0[2], r1[2], r0[3], r1[3]);
            }
            __syncwarp();
        } else {
            __syncthreads();                   // ALL pair-layout reads done before plain writes
#pragma unroll
            for (int pq = 0; pq < PAIRS; ++pq) {
                const int p = w * (2 * PAIRS) + pq * 2;
#pragma unroll
                for (int c = 0; c < 4; ++c) {
                    float2 v = up2(acc[pq][c]);
                    sA[p * ACTP + f0 + c]       = v.x + Bv[c];
                    sA[(p + 1) * ACTP + f0 + c] = v.y + Bv[c];
                }
            }
        }
    }
    __syncthreads();

    // ---- final contraction (f32x2): out[p][o] = sum_h trunk[p][h]*bc[o][h] ----
    if (tid < PTS) {
        const int p = tid;
        u64 q0 = 0ull, q1 = 0ull, q2 = 0ull, q3 = 0ull, q4 = 0ull;
#pragma unroll 4
        for (int h = 0; h < HID; h += 4) {
            ulonglong2 a  = *(const ulonglong2*)&sA[p * ACTP + h];
            ulonglong2 c0 = *(const ulonglong2*)&sC[0 * HID + h];
            ulonglong2 c1 = *(const ulonglong2*)&sC[1 * HID + h];
            ulonglong2 c2 = *(const ulonglong2*)&sC[2 * HID + h];
            ulonglong2 c3 = *(const ulonglong2*)&sC[3 * HID + h];
            ulonglong2 c4 = *(const ulonglong2*)&sC[4 * HID + h];
            fma2(q0, a.x, c0.x); fma2(q0, a.y, c0.y);
            fma2(q1, a.x, c1.x); fma2(q1, a.y, c1.y);
            fma2(q2, a.x, c2.x); fma2(q2, a.y, c2.y);
            fma2(q3, a.x, c3.x); fma2(q3, a.y, c3.y);
            fma2(q4, a.x, c4.x); fma2(q4, a.y, c4.y);
        }
        const int pglob = p0 + p;
        if (pglob < NPTS) {
            float2 v0 = up2(q0), v1 = up2(q1), v2 = up2(q2), v3 = up2(q3), v4 = up2(q4);
            float* dst = out + ((size_t)b * NPTS + pglob) * OUTD;
            dst[0] = v0.x + v0.y; dst[1] = v1.x + v1.y; dst[2] = v2.x + v2.y;
            dst[3] = v3.x + v3.y; dst[4] = v4.x + v4.y;
        }
    }
}

// ---------------------------------------------------------------------------
extern "C" void kernel_launch(void* const* d_in, const int* in_sizes, int n_in,
                              void* d_out, int out_size)
{
    const float* coords = (const float*)d_in[0];
    const float* sdf    = (const float*)d_in[1];
    const float* params = (const float*)d_in[2];
    const float* Wb0    = (const float*)d_in[3];
    const float* bb0    = (const float*)d_in[4];
    const float* Wb     = (const float*)d_in[5];
    const float* bbv    = (const float*)d_in[6];
    const float* Wbf    = (const float*)d_in[7];
    const float* bbf    = (const float*)d_in[8];
    const float* ab     = (const float*)d_in[9];
    const float* wb     = (const float*)d_in[10];
    const float* Wt0    = (const float*)d_in[11];
    const float* bt0    = (const float*)d_in[12];
    const float* Wt     = (const float*)d_in[13];
    const float* bt     = (const float*)d_in[14];
    const float* Wtf    = (const float*)d_in[15];
    const float* btf    = (const float*)d_in[16];
    const float* at     = (const float*)d_in[17];
    const float* wt     = (const float*)d_in[18];
    float* out = (float*)d_out;

    const size_t smem_bytes = (size_t)(HID * HID + 25344 + PTS * 4 + 4 * HID + OUTD * HID) * sizeof(float);
    cudaFuncSetAttribute(trunk_kernel, cudaFuncAttributeMaxDynamicSharedMemorySize, (int)smem_bytes);

    branch_kernel<<<BB, 256>>>(params, Wb0, bb0, Wb, bbv, Wbf, bbf, ab, wb);

    dim3 grid(NT, BB);
    trunk_kernel<<<grid, THR, smem_bytes>>>(coords, sdf, Wt0, bt0, Wt, bt,
                                            Wtf, btf, at, wt, out);
}

// round 10
// speedup vs baseline: 1.5400x; 1.4090x over previous
#include <cuda_runtime.h>
#include <cuda_bf16.h>
#include <cstdint>
#include <cstddef>

#define BB   16
#define NPTS 10000
#define HID  128
#define OUTD 5
#define THR  256
#define PTS  128
#define NBLK 79             // ceil(10000/128)

// scalar region (float indices into sm[])
#define SX_F    0           // 128*4
#define SGATE_F 512         // 4*128
#define SBC_F   1024        // 5*128
#define SBIAS_F 1664        // bt (3*128) + btf (128)
#define SAT_F   2176        // 4*128
#define SWQ_F   2688        // 4*128
#define SW0_F   3200        // 4*128
#define SB0_F   3712        // 128
// byte regions
#define WF_BYTE  15360      // W fragments: 4096 * 16B = 64KB
#define AHI_BYTE 80896      // A hi tile: 128 rows * 272B
#define ALO_BYTE 115712     // A lo tile
#define ABYTES   34816
#define ASTRIDE  272        // 136 bf16 per row (conflict-free ldmatrix)
#define SMEM_BYTES 150528

typedef unsigned long long u64;

__device__ float g_gate[BB * 4 * HID];
__device__ float g_bc[BB * OUTD * HID];
__device__ __align__(16) uint4 g_Wfrag[4][4096];   // [layer][(ks*16+n0)*32+lane]

__device__ __forceinline__ float tanh_ap(float x) {
    float r; asm("tanh.approx.f32 %0, %1;" : "=f"(r) : "f"(x)); return r;
}
__device__ __forceinline__ float sin_ap(float x) {
    float r; asm("sin.approx.f32 %0, %1;" : "=f"(r) : "f"(x)); return r;
}
__device__ __forceinline__ uint32_t smem_u32(const void* p) {
    uint32_t a;
    asm("{ .reg .u64 t; cvta.to.shared.u64 t, %1; cvt.u32.u64 %0, t; }" : "=r"(a) : "l"(p));
    return a;
}
// pack two f32 -> bf16x2; e0 -> low half (smaller k), e1 -> high half
__device__ __forceinline__ uint32_t pkbf(float e0, float e1) {
    uint32_t r; asm("cvt.rn.satfinite.bf16x2.f32 %0, %1, %2;" : "=r"(r) : "f"(e1), "f"(e0));
    return r;
}
__device__ __forceinline__ void split2(float v, float& hf, float& lf) {
    __nv_bfloat16 h = __float2bfloat16_rn(v);
    hf = __bfloat162float(h);
    lf = v - hf;
}
__device__ __forceinline__ void ldmat4(uint32_t* r, uint32_t addr) {
    asm volatile("ldmatrix.sync.aligned.m8n8.x4.shared.b16 {%0,%1,%2,%3}, [%4];"
                 : "=r"(r[0]), "=r"(r[1]), "=r"(r[2]), "=r"(r[3]) : "r"(addr));
}
__device__ __forceinline__ void hmma(float (&d)[4], const uint32_t* a, uint32_t b0, uint32_t b1) {
    asm volatile(
        "mma.sync.aligned.m16n8k16.row.col.f32.bf16.bf16.f32 "
        "{%0,%1,%2,%3}, {%4,%5,%6,%7}, {%8,%9}, {%0,%1,%2,%3};"
        : "+f"(d[0]), "+f"(d[1]), "+f"(d[2]), "+f"(d[3])
        : "r"(a[0]), "r"(a[1]), "r"(a[2]), "r"(a[3]), "r"(b0), "r"(b1));
}
__device__ __forceinline__ void fma2(u64& d, u64 a, u64 b) {
    asm("fma.rn.f32x2 %0, %1, %2, %0;" : "+l"(d) : "l"(a), "l"(b));
}
__device__ __forceinline__ float2 up2(u64 v) {
    float2 r; asm("mov.b64 {%0, %1}, %2;" : "=f"(r.x), "=f"(r.y) : "l"(v)); return r;
}

// ---------------------------------------------------------------------------
// Weight prep: pack W (as mma B operand, col-layout) into per-lane fragment
// quads {Whi_b0, Whi_b1, Wlo_b0, Wlo_b1} so the GEMM does 1 LDS.128 per tile.
// B[k][n] = W[k][n] (W row-major [in][out]).
// ---------------------------------------------------------------------------
__global__ void wprep_kernel(const float* __restrict__ Wt, const float* __restrict__ Wtf) {
    const int l = blockIdx.x;
    const float* W = (l < 3) ? (Wt + (size_t)l * HID * HID) : Wtf;
    for (int e = threadIdx.x; e < 4096; e += 256) {
        int ks = e >> 9, n0 = (e >> 5) & 15, t = e & 31;
        int n  = n0 * 8 + (t >> 2);
        int kb = ks * 16 + (t & 3) * 2;
        float w00 = W[(size_t)kb * HID + n],       w01 = W[(size_t)(kb + 1) * HID + n];
        float w10 = W[(size_t)(kb + 8) * HID + n], w11 = W[(size_t)(kb + 9) * HID + n];
        float h00, l00, h01, l01, h10, l10, h11, l11;
        split2(w00, h00, l00); split2(w01, h01, l01);
        split2(w10, h10, l10); split2(w11, h11, l11);
        uint4 u;
        u.x = pkbf(h00, h01); u.y = pkbf(h10, h11);
        u.z = pkbf(l00, l01); u.w = pkbf(l10, l11);
        g_Wfrag[l][e] = u;
    }
}

// ---------------------------------------------------------------------------
// Branch MLP (unchanged)
// ---------------------------------------------------------------------------
__global__ void branch_kernel(const float* __restrict__ params,
                              const float* __restrict__ Wb0, const float* __restrict__ bb0,
                              const float* __restrict__ Wb,  const float* __restrict__ bbv,
                              const float* __restrict__ Wbf, const float* __restrict__ bbf,
                              const float* __restrict__ ab,  const float* __restrict__ wb)
{
    __shared__ float h_s[HID];
    __shared__ float part[HID];
    const int b = blockIdx.x, tid = threadIdx.x;
    const int j = tid & 127, hh = tid >> 7;

    float g = 0.f;
    if (hh == 0) {
        float z = bb0[j];
#pragma unroll
        for (int c = 0; c < 6; ++c) z = fmaf(params[b * 6 + c], Wb0[c * HID + j], z);
        float v = tanh_ap(z) + ab[j] * sin_ap(wb[j] * z);
        g = v; g_gate[(b * 4) * HID + j] = g; h_s[j] = v;
    }
    __syncthreads();

    for (int i = 0; i < 3; ++i) {
        const float* W = Wb + (size_t)i * HID * HID;
        float zz = (hh == 0) ? bbv[i * HID + j] : 0.f;
        const int k0 = hh * 64;
#pragma unroll 4
        for (int k = 0; k < 64; ++k) zz = fmaf(h_s[k0 + k], W[(size_t)(k0 + k) * HID + j], zz);
        if (hh) part[j] = zz;
        __syncthreads();
        float v = 0.f;
        if (hh == 0) {
            float z = zz + part[j];
            v = tanh_ap(z) + ab[(i + 1) * HID + j] * sin_ap(wb[(i + 1) * HID + j] * z);
            g += v; g_gate[(b * 4 + i + 1) * HID + j] = g;
        }
        __syncthreads();
        if (hh == 0) h_s[j] = v;
        __syncthreads();
    }

#pragma unroll
    for (int o = 0; o < OUTD; ++o) {
        float zz = (hh == 0) ? bbf[o * HID + j] : 0.f;
        const int k0 = hh * 64;
#pragma unroll 4
        for (int k = 0; k < 64; ++k)
            zz = fmaf(h_s[k0 + k], Wbf[(size_t)(k0 + k) * (HID * OUTD) + o * HID + j], zz);
        if (hh) part[j] = zz;
        __syncthreads();
        if (hh == 0) g_bc[(b * OUTD + o) * HID + j] = zz + part[j];
        __syncthreads();
    }
}

// ---------------------------------------------------------------------------
// Trunk: 128 pts/block, 8 warps. Warp w owns rows [16w,16w+16). bf16-split
// GEMMs via mma.sync m16n8k16 (3 passes into fp32 accum). Epilogues are
// warp-private; block syncs only around W-fragment staging.
// ---------------------------------------------------------------------------
__global__ void __launch_bounds__(THR, 1)
trunk_kernel(const float* __restrict__ coords, const float* __restrict__ sdf,
             const float* __restrict__ Wt0, const float* __restrict__ bt0,
             const float* __restrict__ btv, const float* __restrict__ btf,
             const float* __restrict__ at,  const float* __restrict__ wt,
             float* __restrict__ out)
{
    extern __shared__ float sm[];
    char* smc = (char*)sm;
    const uint32_t sbase = smem_u32(sm);

    const int b    = blockIdx.y;
    const int p0   = blockIdx.x * PTS;
    const int tid  = threadIdx.x;
    const int warp = tid >> 5;
    const int lane = tid & 31;

    // stage inputs + scalars
    if (tid < PTS) {
        int p = p0 + tid;
        float4 v = make_float4(0.f, 0.f, 0.f, 0.f);
        if (p < NPTS) {
            const float* c = coords + ((size_t)b * NPTS + p) * 3;
            v.x = c[0]; v.y = c[1]; v.z = c[2];
            v.w = sdf[(size_t)b * NPTS + p];
        }
        ((float4*)&sm[SX_F])[tid] = v;
    }
    for (int i = tid; i < 512; i += THR) sm[SGATE_F + i] = g_gate[b * 512 + i];
    for (int i = tid; i < 640; i += THR) sm[SBC_F + i]   = g_bc[b * 640 + i];
    for (int i = tid; i < 384; i += THR) sm[SBIAS_F + i] = btv[i];
    for (int i = tid; i < 128; i += THR) sm[SBIAS_F + 384 + i] = btf[i];
    for (int i = tid; i < 512; i += THR) sm[SAT_F + i] = at[i];
    for (int i = tid; i < 512; i += THR) sm[SWQ_F + i] = wt[i];
    for (int i = tid; i < 512; i += THR) sm[SW0_F + i] = Wt0[i];
    for (int i = tid; i < 128; i += THR) sm[SB0_F + i] = bt0[i];
    __syncthreads();

    char* AhiC = smc + AHI_BYTE;
    char* AloC = smc + ALO_BYTE;

    // ---- layer 0: thread t handles point r=t/2, column half ch=t&1 ----
    {
        const int r = tid >> 1, ch = tid & 1;
        float4 xv = ((float4*)&sm[SX_F])[r];
#pragma unroll 1
        for (int j0 = ch * 64; j0 < ch * 64 + 64; j0 += 8) {
            float hf[8], lf[8];
#pragma unroll
            for (int jj = 0; jj < 8; ++jj) {
                int j = j0 + jj;
                float z = fmaf(xv.x, sm[SW0_F + j],
                          fmaf(xv.y, sm[SW0_F + 128 + j],
                          fmaf(xv.z, sm[SW0_F + 256 + j],
                          fmaf(xv.w, sm[SW0_F + 384 + j], sm[SB0_F + j]))));
                float v = (tanh_ap(z) + sm[SAT_F + j] * sin_ap(sm[SWQ_F + j] * z)) * sm[SGATE_F + j];
                split2(v, hf[jj], lf[jj]);
            }
            uint4 hq, lq;
            hq.x = pkbf(hf[0], hf[1]); hq.y = pkbf(hf[2], hf[3]);
            hq.z = pkbf(hf[4], hf[5]); hq.w = pkbf(hf[6], hf[7]);
            lq.x = pkbf(lf[0], lf[1]); lq.y = pkbf(lf[2], lf[3]);
            lq.z = pkbf(lf[4], lf[5]); lq.w = pkbf(lf[6], lf[7]);
            *(uint4*)(AhiC + r * ASTRIDE + j0 * 2) = hq;
            *(uint4*)(AloC + r * ASTRIDE + j0 * 2) = lq;
        }
    }
    // rows of warp w are written only by warp w's threads -> warp-local hazard
    __syncwarp();

    const int r0 = warp * 16;
    const int qm = lane & 3, qr = lane >> 2;
    const uint32_t a_base = sbase + AHI_BYTE + (uint32_t)(r0 + (lane & 15)) * ASTRIDE
                          + (uint32_t)(lane >> 4) * 16;

    // ---- layers 1..3 (Wt[0..2], rowdy*gate) + final linear (Wtf) ----
    for (int L = 0; L < 4; ++L) {
        const bool fin = (L == 3);

        __syncthreads();                 // all warps done with prev W frags
        {
            const uint4* src = g_Wfrag[L];
            uint4* dst = (uint4*)(smc + WF_BYTE);
            for (int i = tid; i < 4096; i += THR) dst[i] = src[i];
        }
        __syncthreads();                 // W frags ready

        float d[16][4];
#pragma unroll
        for (int n0 = 0; n0 < 16; ++n0)
#pragma unroll
            for (int c = 0; c < 4; ++c) d[n0][c] = 0.f;

        const uint4* sWf = (const uint4*)(smc + WF_BYTE);
#pragma unroll 1
        for (int ks = 0; ks < 8; ++ks) {
            uint32_t ah[4], al[4];
            uint32_t aaddr = a_base + (uint32_t)ks * 32;
            ldmat4(ah, aaddr);
            ldmat4(al, aaddr + ABYTES);
            const uint4* wrow = sWf + (ks * 16) * 32 + lane;
#pragma unroll
            for (int n0 = 0; n0 < 16; ++n0) {
                uint4 wv = wrow[n0 * 32];
                hmma(d[n0], ah, wv.x, wv.y);   // hi * Whi
                hmma(d[n0], al, wv.x, wv.y);   // lo * Whi
                hmma(d[n0], ah, wv.z, wv.w);   // hi * Wlo
            }
        }

        const int ra = r0 + qr, rb = ra + 8;
        if (!fin) {
            const int bofs = SBIAS_F + L * 128;
            const int aofs = SAT_F + (L + 1) * 128;
            const int qofs = SWQ_F + (L + 1) * 128;
            const int gofs = SGATE_F + (L + 1) * 128;
#pragma unroll
            for (int n0 = 0; n0 < 16; ++n0) {
                const int cb = n0 * 8 + qm * 2;
                float2 bi = *(const float2*)&sm[bofs + cb];
                float2 av = *(const float2*)&sm[aofs + cb];
                float2 qv = *(const float2*)&sm[qofs + cb];
                float2 gv = *(const float2*)&sm[gofs + cb];
                float z0 = d[n0][0] + bi.x, z1 = d[n0][1] + bi.y;
                float z2 = d[n0][2] + bi.x, z3 = d[n0][3] + bi.y;
                float v0 = (tanh_ap(z0) + av.x * sin_ap(qv.x * z0)) * gv.x;
                float v1 = (tanh_ap(z1) + av.y * sin_ap(qv.y * z1)) * gv.y;
                float v2 = (tanh_ap(z2) + av.x * sin_ap(qv.x * z2)) * gv.x;
                float v3 = (tanh_ap(z3) + av.y * sin_ap(qv.y * z3)) * gv.y;
                float h0, l0, h1, l1, h2, l2, h3, l3;
                split2(v0, h0, l0); split2(v1, h1, l1);
                split2(v2, h2, l2); split2(v3, h3, l3);
                *(uint32_t*)(AhiC + ra * ASTRIDE + cb * 2) = pkbf(h0, h1);
                *(uint32_t*)(AhiC + rb * ASTRIDE + cb * 2) = pkbf(h2, h3);
                *(uint32_t*)(AloC + ra * ASTRIDE + cb * 2) = pkbf(l0, l1);
                *(uint32_t*)(AloC + rb * ASTRIDE + cb * 2) = pkbf(l2, l3);
            }
            __syncwarp();                // warp-private rows; next ldmatrix same warp
        } else {
            __syncthreads();             // everyone done reading A -> reuse as fp32
            float* sAct = (float*)(smc + AHI_BYTE);   // [128][132] floats
#pragma unroll
            for (int n0 = 0; n0 < 16; ++n0) {
                const int cb = n0 * 8 + qm * 2;
                float2 bt2 = *(const float2*)&sm[SBIAS_F + 384 + cb];
                *(float2*)&sAct[ra * 132 + cb] = make_float2(d[n0][0] + bt2.x, d[n0][1] + bt2.y);
                *(float2*)&sAct[rb * 132 + cb] = make_float2(d[n0][2] + bt2.x, d[n0][3] + bt2.y);
            }
            __syncthreads();

            // final contraction: out[p][o] = sum_h trunk[p][h] * bc[o][h]
            if (tid < PTS) {
                const int p = tid;
                u64 q0 = 0ull, q1 = 0ull, q2 = 0ull, q3 = 0ull, q4 = 0ull;
#pragma unroll 4
                for (int h = 0; h < HID; h += 4) {
                    ulonglong2 a  = *(const ulonglong2*)&sAct[p * 132 + h];
                    ulonglong2 c0 = *(const ulonglong2*)&sm[SBC_F + 0 * 128 + h];
                    ulonglong2 c1 = *(const ulonglong2*)&sm[SBC_F + 1 * 128 + h];
                    ulonglong2 c2 = *(const ulonglong2*)&sm[SBC_F + 2 * 128 + h];
                    ulonglong2 c3 = *(const ulonglong2*)&sm[SBC_F + 3 * 128 + h];
                    ulonglong2 c4 = *(const ulonglong2*)&sm[SBC_F + 4 * 128 + h];
                    fma2(q0, a.x, c0.x); fma2(q0, a.y, c0.y);
                    fma2(q1, a.x, c1.x); fma2(q1, a.y, c1.y);
                    fma2(q2, a.x, c2.x); fma2(q2, a.y, c2.y);
                    fma2(q3, a.x, c3.x); fma2(q3, a.y, c3.y);
                    fma2(q4, a.x, c4.x); fma2(q4, a.y, c4.y);
                }
                const int pglob = p0 + p;
                if (pglob < NPTS) {
                    float2 v0 = up2(q0), v1 = up2(q1), v2 = up2(q2), v3 = up2(q3), v4 = up2(q4);
                    float* dst = out + ((size_t)b * NPTS + pglob) * OUTD;
                    dst[0] = v0.x + v0.y; dst[1] = v1.x + v1.y; dst[2] = v2.x + v2.y;
                    dst[3] = v3.x + v3.y; dst[4] = v4.x + v4.y;
                }
            }
        }
    }
}

// ---------------------------------------------------------------------------
extern "C" void kernel_launch(void* const* d_in, const int* in_sizes, int n_in,
                              void* d_out, int out_size)
{
    const float* coords = (const float*)d_in[0];
    const float* sdf    = (const float*)d_in[1];
    const float* params = (const float*)d_in[2];
    const float* Wb0    = (const float*)d_in[3];
    const float* bb0    = (const float*)d_in[4];
    const float* Wb     = (const float*)d_in[5];
    const float* bbv    = (const float*)d_in[6];
    const float* Wbf    = (const float*)d_in[7];
    const float* bbf    = (const float*)d_in[8];
    const float* ab     = (const float*)d_in[9];
    const float* wb     = (const float*)d_in[10];
    const float* Wt0    = (const float*)d_in[11];
    const float* bt0    = (const float*)d_in[12];
    const float* Wt     = (const float*)d_in[13];
    const float* bt     = (const float*)d_in[14];
    const float* Wtf    = (const float*)d_in[15];
    const float* btf    = (const float*)d_in[16];
    const float* at     = (const float*)d_in[17];
    const float* wt     = (const float*)d_in[18];
    float* out = (float*)d_out;

    cudaFuncSetAttribute(trunk_kernel, cudaFuncAttributeMaxDynamicSharedMemorySize, SMEM_BYTES);

    wprep_kernel<<<4, 256>>>(Wt, Wtf);
    branch_kernel<<<BB, 256>>>(params, Wb0, bb0, Wb, bbv, Wbf, bbf, ab, wb);

    dim3 grid(NBLK, BB);
    trunk_kernel<<<grid, THR, SMEM_BYTES>>>(coords, sdf, Wt0, bt0, bt, btf,
                                            at, wt, out);
}